// round 4
// baseline (speedup 1.0000x reference)
#include <cuda_runtime.h>
#include <cuda_fp16.h>
#include <cstdint>
#include <math.h>

#define BB 4
#define LL 2048
#define DD 1024
#define HH 16
#define KK 256
#define DH 64
#define MROWS (BB*LL)   // 8192

// ---- scratch (device globals; no runtime allocation allowed) ----
__device__ float  g_q[BB*LL*DD];          // x @ Wq^T  [B,L,D] f32
__device__ __half g_xh[BB*LL*DD];         // x hi/lo
__device__ __half g_xl[BB*LL*DD];
__device__ __half g_wqh[DD*DD], g_wql[DD*DD];
__device__ __half g_wkh[DD*DD], g_wkl[DD*DD];
__device__ __half g_wvh[DD*DD], g_wvl[DD*DD];
__device__ __half g_woh[DD*DD], g_wol[DD*DD];
__device__ __half g_pkth[KK*LL], g_pktl[KK*LL];   // proj_k^T hi/lo [K,L]
__device__ __half g_pvth[KK*LL], g_pvtl[KK*LL];
__device__ __half g_xkth[BB*DD*LL], g_xktl[BB*DD*LL];  // (xWk^T)^T hi/lo [B,D,L]
__device__ __half g_xvth[BB*DD*LL], g_xvtl[BB*DD*LL];
__device__ float  g_keys2[2*BB*DD*KK];    // split-K partials
__device__ float  g_vals2[2*BB*KK*DD];
__device__ float  g_keys_t[BB*DD*KK];     // [B,D,K] f32
__device__ float  g_vals[BB*KK*DD];       // [B,K,D] f32
__device__ __half g_ctxh[BB*LL*DD], g_ctxl[BB*LL*DD];  // attention out hi/lo

// ============================================================
// helpers
// ============================================================
__device__ __forceinline__ uint32_t smem_u32(const void* p) {
    uint32_t a;
    asm("{ .reg .u64 t; cvta.to.shared.u64 t, %1; cvt.u32.u64 %0, t; }"
        : "=r"(a) : "l"(p));
    return a;
}
__device__ __forceinline__ void ldsm4(uint32_t* r, uint32_t addr) {
    asm volatile("ldmatrix.sync.aligned.m8n8.x4.shared.b16 {%0,%1,%2,%3}, [%4];"
        : "=r"(r[0]), "=r"(r[1]), "=r"(r[2]), "=r"(r[3]) : "r"(addr));
}
__device__ __forceinline__ void ldsm2(uint32_t* r, uint32_t addr) {
    asm volatile("ldmatrix.sync.aligned.m8n8.x2.shared.b16 {%0,%1}, [%2];"
        : "=r"(r[0]), "=r"(r[1]) : "r"(addr));
}
__device__ __forceinline__ void mma16816(float* c, const uint32_t* a, const uint32_t* b) {
    asm volatile(
        "mma.sync.aligned.m16n8k16.row.col.f32.f16.f16.f32 "
        "{%0,%1,%2,%3}, {%4,%5,%6,%7}, {%8,%9}, {%0,%1,%2,%3};"
        : "+f"(c[0]), "+f"(c[1]), "+f"(c[2]), "+f"(c[3])
        : "r"(a[0]), "r"(a[1]), "r"(a[2]), "r"(a[3]), "r"(b[0]), "r"(b[1]));
}
__device__ __forceinline__ void cp16(uint32_t sa, const void* ga) {
    asm volatile("cp.async.cg.shared.global [%0], [%1], 16;" :: "r"(sa), "l"(ga));
}
#define CP_COMMIT() asm volatile("cp.async.commit_group;" ::: "memory")
#define CP_WAIT0()  asm volatile("cp.async.wait_group 0;" ::: "memory")
#define CP_WAIT1()  asm volatile("cp.async.wait_group 1;" ::: "memory")

// ============================================================
// split-fp16 NT-GEMM with pre-split half planes + cp.async pipeline.
// C[m,n] = sum_k A[m,k]*B[n,k], A~Ah+Al, B~Bh+Bl, 3 MMAs (drop lo*lo).
// CTA 128x128, BK=32, 8 warps (warp tile 64x32), 2 stages, 2 CTAs/SM.
// ============================================================
#define TPADH 40                       // halves per smem row (32+8 pad)
#define TILEB (128*TPADH*2)            // 10240 bytes per tile
#define STGB  (4*TILEB)                // 40960 bytes per stage
#define GEMM_SMEM (2*STGB)             // 81920

template<bool BIAS, int OUTMODE>       // OUTMODE 0: f32, 1: half-split
__global__ __launch_bounds__(256, 2)
void gemm_hsplit(const __half* __restrict__ Ah, const __half* __restrict__ Al,
                 long Ab, int lda,
                 const __half* __restrict__ Bh, const __half* __restrict__ Bl,
                 long Bb, int ldb,
                 void* C0, void* C1, long Cb, long Cs, int ldc,
                 const float* __restrict__ bias, int Kd, int ksp)
{
    extern __shared__ __align__(16) char smc[];
    const uint32_t sbase = smem_u32(smc);

    const int tid  = threadIdx.x;
    const int lane = tid & 31;
    const int wid  = tid >> 5;
    const int wm   = wid >> 2;          // 0..1
    const int wn   = wid & 3;           // 0..3

    const int zb = blockIdx.z / ksp;
    const int zs = blockIdx.z % ksp;
    Ah += (size_t)zb * Ab + (size_t)zs * Kd;
    Al += (size_t)zb * Ab + (size_t)zs * Kd;
    Bh += (size_t)zb * Bb + (size_t)zs * Kd;
    Bl += (size_t)zb * Bb + (size_t)zs * Kd;
    const int m0 = blockIdx.y * 128;
    const int n0 = blockIdx.x * 128;

    // per-thread cp.async source pointers / smem offsets (8 x 16B per stage)
    const int seg = tid & 3;
    const int rr  = tid >> 2;           // 0..63
    const __half* gp[8];
    gp[0] = Ah + (size_t)(m0 + rr)      * lda + seg * 8;
    gp[1] = Ah + (size_t)(m0 + rr + 64) * lda + seg * 8;
    gp[2] = Al + (size_t)(m0 + rr)      * lda + seg * 8;
    gp[3] = Al + (size_t)(m0 + rr + 64) * lda + seg * 8;
    gp[4] = Bh + (size_t)(n0 + rr)      * ldb + seg * 8;
    gp[5] = Bh + (size_t)(n0 + rr + 64) * ldb + seg * 8;
    gp[6] = Bl + (size_t)(n0 + rr)      * ldb + seg * 8;
    gp[7] = Bl + (size_t)(n0 + rr + 64) * ldb + seg * 8;
    uint32_t so[8];
    #pragma unroll
    for (int p = 0; p < 8; p++)
        so[p] = (uint32_t)((p >> 1) * TILEB + (rr + (p & 1) * 64) * (TPADH*2) + seg * 16);

    float acc[4][4][4];
    #pragma unroll
    for (int i = 0; i < 4; i++)
        #pragma unroll
        for (int j = 0; j < 4; j++)
            #pragma unroll
            for (int v = 0; v < 4; v++) acc[i][j][v] = 0.f;

    auto load_stage = [&](int s, int it) {
        const int k0 = it * 32;
        const uint32_t base = sbase + s * STGB;
        #pragma unroll
        for (int p = 0; p < 8; p++)
            cp16(base + so[p], gp[p] + k0);
        CP_COMMIT();
    };

    auto compute = [&](int s) {
        const uint32_t aHi = sbase + s * STGB;
        const uint32_t aLo = aHi + TILEB;
        const uint32_t bHi = aHi + 2 * TILEB;
        const uint32_t bLo = aHi + 3 * TILEB;
        #pragma unroll
        for (int ks = 0; ks < 2; ks++) {
            uint32_t ah[4][4], al[4][4], bh[4][2], bl[4][2];
            const int acol = ks * 16 + (lane >> 4) * 8;
            #pragma unroll
            for (int mi = 0; mi < 4; mi++) {
                int r = wm * 64 + mi * 16 + (lane & 15);
                uint32_t off = (uint32_t)(r * TPADH + acol) * 2;
                ldsm4(ah[mi], aHi + off);
                ldsm4(al[mi], aLo + off);
            }
            const int bcol = ks * 16 + ((lane >> 3) & 1) * 8;
            #pragma unroll
            for (int ni = 0; ni < 4; ni++) {
                int r = wn * 32 + ni * 8 + (lane & 7);
                uint32_t off = (uint32_t)(r * TPADH + bcol) * 2;
                ldsm2(bh[ni], bHi + off);
                ldsm2(bl[ni], bLo + off);
            }
            #pragma unroll
            for (int mi = 0; mi < 4; mi++)
                #pragma unroll
                for (int ni = 0; ni < 4; ni++) {
                    mma16816(acc[mi][ni], ah[mi], bh[ni]);
                    mma16816(acc[mi][ni], ah[mi], bl[ni]);
                    mma16816(acc[mi][ni], al[mi], bh[ni]);
                }
        }
    };

    const int iters = Kd / 32;
    load_stage(0, 0);
    for (int it = 0; it < iters; it++) {
        const bool more = (it + 1 < iters);
        if (more) load_stage((it + 1) & 1, it + 1);
        if (more) CP_WAIT1(); else CP_WAIT0();
        __syncthreads();
        compute(it & 1);
        __syncthreads();
    }

    // ---- epilogue ----
    const int g = lane >> 2, tig = lane & 3;
    if (OUTMODE == 0) {
        float* Cf = (float*)C0 + (size_t)zb * Cb + (size_t)zs * Cs;
        #pragma unroll
        for (int mi = 0; mi < 4; mi++) {
            const int r0 = m0 + wm * 64 + mi * 16 + g;
            #pragma unroll
            for (int ni = 0; ni < 4; ni++) {
                const int col = n0 + wn * 32 + ni * 8 + tig * 2;
                float2 v0, v1;
                v0.x = acc[mi][ni][0]; v0.y = acc[mi][ni][1];
                v1.x = acc[mi][ni][2]; v1.y = acc[mi][ni][3];
                if (BIAS) {
                    float2 bv = *(const float2*)(bias + col);
                    v0.x += bv.x; v0.y += bv.y;
                    v1.x += bv.x; v1.y += bv.y;
                }
                *(float2*)(Cf + (size_t)r0 * ldc + col) = v0;
                *(float2*)(Cf + (size_t)(r0 + 8) * ldc + col) = v1;
            }
        }
    } else {
        __half* Ch = (__half*)C0 + (size_t)zb * Cb;
        __half* Cl = (__half*)C1 + (size_t)zb * Cb;
        #pragma unroll
        for (int mi = 0; mi < 4; mi++) {
            const int r0 = m0 + wm * 64 + mi * 16 + g;
            #pragma unroll
            for (int ni = 0; ni < 4; ni++) {
                const int col = n0 + wn * 32 + ni * 8 + tig * 2;
                #pragma unroll
                for (int hv = 0; hv < 2; hv++) {
                    const int r = r0 + hv * 8;
                    float vx = acc[mi][ni][hv*2], vy = acc[mi][ni][hv*2+1];
                    __half2 h = __floats2half2_rn(vx, vy);
                    float2 bk = __half22float2(h);
                    __half2 l = __floats2half2_rn(vx - bk.x, vy - bk.y);
                    *(__half2*)(Ch + (size_t)r * ldc + col) = h;
                    *(__half2*)(Cl + (size_t)r * ldc + col) = l;
                }
            }
        }
    }
}

// ============================================================
// elementwise split f32 -> hi/lo half planes
// ============================================================
__global__ __launch_bounds__(256)
void convert_split(const float* __restrict__ s, __half* __restrict__ hi,
                   __half* __restrict__ lo, int n4)
{
    int i = blockIdx.x * blockDim.x + threadIdx.x;
    if (i >= n4) return;
    float4 v = *(const float4*)(s + i * 4);
    __half2 h0 = __floats2half2_rn(v.x, v.y);
    __half2 h1 = __floats2half2_rn(v.z, v.w);
    float2 b0 = __half22float2(h0);
    float2 b1 = __half22float2(h1);
    __half2 l0 = __floats2half2_rn(v.x - b0.x, v.y - b0.y);
    __half2 l1 = __floats2half2_rn(v.z - b1.x, v.w - b1.y);
    *(__half2*)(hi + i * 4)     = h0;
    *(__half2*)(hi + i * 4 + 2) = h1;
    *(__half2*)(lo + i * 4)     = l0;
    *(__half2*)(lo + i * 4 + 2) = l1;
}

// ============================================================
// proj transpose + split: [L,K] f32 -> [K,L] hi/lo halves
// ============================================================
__global__ __launch_bounds__(256)
void transpose_split(const float* __restrict__ pk, const float* __restrict__ pv,
                     __half* __restrict__ kh, __half* __restrict__ kl,
                     __half* __restrict__ vh, __half* __restrict__ vl)
{
    __shared__ float t[32][33];
    const float* src = blockIdx.z ? pv : pk;
    __half* dh = blockIdx.z ? vh : kh;
    __half* dl = blockIdx.z ? vl : kl;
    int k0 = blockIdx.x * 32, l0 = blockIdx.y * 32;
    int tx = threadIdx.x, ty = threadIdx.y;
    #pragma unroll
    for (int i = 0; i < 32; i += 8)
        t[ty + i][tx] = src[(size_t)(l0 + ty + i) * KK + k0 + tx];
    __syncthreads();
    #pragma unroll
    for (int i = 0; i < 32; i += 8) {
        float v = t[tx][ty + i];
        __half h = __float2half_rn(v);
        __half l = __float2half_rn(v - __half2float(h));
        size_t o = (size_t)(k0 + ty + i) * LL + l0 + tx;
        dh[o] = h; dl[o] = l;
    }
}

// ============================================================
// add split-K partials: o = a + b  (float4)
// ============================================================
__global__ __launch_bounds__(256)
void add2(const float* __restrict__ a, const float* __restrict__ b,
          float* __restrict__ o, int n4)
{
    int i = blockIdx.x * blockDim.x + threadIdx.x;
    if (i >= n4) return;
    float4 x = *(const float4*)(a + i * 4);
    float4 y = *(const float4*)(b + i * 4);
    x.x += y.x; x.y += y.y; x.z += y.z; x.w += y.w;
    *(float4*)(o + i * 4) = x;
}

// ============================================================
// Attention (fp32 SIMT, R1-verified) — epilogue now emits ctx hi/lo halves
// ============================================================
#define QS_STRIDE 68
#define KS_STRIDE 264
#define VS_STRIDE 68
#define PS_STRIDE 264
#define ATTN_SMEM ((64*QS_STRIDE + 64*KS_STRIDE + 256*VS_STRIDE + 64*PS_STRIDE) * 4)

__global__ __launch_bounds__(256)
void attn_kernel()
{
    extern __shared__ float smf[];
    float* Qs = smf;
    float* Ks = Qs + 64*QS_STRIDE;
    float* Vs = Ks + 64*KS_STRIDE;
    float* Ps = Vs + 256*VS_STRIDE;

    const int b  = blockIdx.z;
    const int h  = blockIdx.y;
    const int l0 = blockIdx.x * 64;
    const int tid = threadIdx.x;

    #pragma unroll
    for (int it = 0; it < 4; it++) {
        int idx = tid + it * 256;
        int r  = idx >> 4;
        int dq = (idx & 15) * 4;
        int l  = l0 + r;
        const float* src = g_q + ((size_t)(b * LL) + h * 128 + (l >> 4)) * DD
                               + (l & 15) * DH + dq;
        *(float4*)&Qs[r * QS_STRIDE + dq] = *(const float4*)src;
    }
    #pragma unroll
    for (int it = 0; it < 16; it++) {
        int idx = tid + it * 256;
        int kd = idx >> 6;
        int c4 = (idx & 63) * 4;
        *(float4*)&Ks[kd * KS_STRIDE + c4] =
            *(const float4*)&g_keys_t[((size_t)b * DD + h * DH + kd) * KK + c4];
    }
    #pragma unroll
    for (int it = 0; it < 16; it++) {
        int idx = tid + it * 256;
        int col = idx >> 4;
        int dq  = (idx & 15) * 4;
        *(float4*)&Vs[col * VS_STRIDE + dq] =
            *(const float4*)&g_vals[((size_t)b * KK + col) * DD + h * DH + dq];
    }
    __syncthreads();

    const int tx = tid & 31, wy = tid >> 5;
    float acc[8][8] = {};
    #pragma unroll 4
    for (int kd = 0; kd < 64; kd++) {
        float a[8], bq[8];
        #pragma unroll
        for (int i = 0; i < 8; i++) a[i] = Qs[(wy*8 + i) * QS_STRIDE + kd];
        *(float4*)&bq[0] = *(const float4*)&Ks[kd * KS_STRIDE + tx*8];
        *(float4*)&bq[4] = *(const float4*)&Ks[kd * KS_STRIDE + tx*8 + 4];
        #pragma unroll
        for (int i = 0; i < 8; i++)
            #pragma unroll
            for (int j = 0; j < 8; j++)
                acc[i][j] += a[i] * bq[j];
    }

    const float SCALE = 0.125f;
    #pragma unroll
    for (int i = 0; i < 8; i++) {
        float mx = -1e30f;
        #pragma unroll
        for (int j = 0; j < 8; j++) {
            acc[i][j] *= SCALE;
            mx = fmaxf(mx, acc[i][j]);
        }
        #pragma unroll
        for (int o = 16; o > 0; o >>= 1)
            mx = fmaxf(mx, __shfl_xor_sync(0xffffffffu, mx, o));
        float s = 0.f;
        #pragma unroll
        for (int j = 0; j < 8; j++) {
            acc[i][j] = __expf(acc[i][j] - mx);
            s += acc[i][j];
        }
        #pragma unroll
        for (int o = 16; o > 0; o >>= 1)
            s += __shfl_xor_sync(0xffffffffu, s, o);
        float inv = 1.f / s;
        float4 p0, p1;
        p0.x = acc[i][0]*inv; p0.y = acc[i][1]*inv; p0.z = acc[i][2]*inv; p0.w = acc[i][3]*inv;
        p1.x = acc[i][4]*inv; p1.y = acc[i][5]*inv; p1.z = acc[i][6]*inv; p1.w = acc[i][7]*inv;
        *(float4*)&Ps[(wy*8 + i) * PS_STRIDE + tx*8    ] = p0;
        *(float4*)&Ps[(wy*8 + i) * PS_STRIDE + tx*8 + 4] = p1;
    }
    __syncthreads();

    float o0[8] = {}, o1[8] = {};
    #pragma unroll 4
    for (int j = 0; j < 256; j++) {
        float2 v = *(const float2*)&Vs[j * VS_STRIDE + tx*2];
        #pragma unroll
        for (int i = 0; i < 8; i++) {
            float p = Ps[(wy*8 + i) * PS_STRIDE + j];
            o0[i] += p * v.x;
            o1[i] += p * v.y;
        }
    }
    #pragma unroll
    for (int i = 0; i < 8; i++) {
        int l = l0 + wy*8 + i;
        size_t o = ((size_t)(b * LL) + l) * DD + h * DH + tx*2;
        __half2 hx = __floats2half2_rn(o0[i], o1[i]);
        float2 bk = __half22float2(hx);
        __half2 lx = __floats2half2_rn(o0[i] - bk.x, o1[i] - bk.y);
        *(__half2*)(g_ctxh + o) = hx;
        *(__half2*)(g_ctxl + o) = lx;
    }
}

// ============================================================
extern "C" void kernel_launch(void* const* d_in, const int* in_sizes, int n_in,
                              void* d_out, int out_size)
{
    const float* x      = (const float*)d_in[0];
    const float* Wq     = (const float*)d_in[1];
    const float* Wk     = (const float*)d_in[2];
    const float* Wv     = (const float*)d_in[3];
    const float* proj_k = (const float*)d_in[4];
    const float* proj_v = (const float*)d_in[5];
    const float* Wo     = (const float*)d_in[6];
    const float* bo     = (const float*)d_in[7];
    float* out = (float*)d_out;

    float *q, *keys2, *vals2, *keys_t, *vals;
    __half *xh, *xl, *wqh, *wql, *wkh, *wkl, *wvh, *wvl, *woh, *wol;
    __half *pkth, *pktl, *pvth, *pvtl, *xkth, *xktl, *xvth, *xvtl, *ctxh, *ctxl;
    cudaGetSymbolAddress((void**)&q,      g_q);
    cudaGetSymbolAddress((void**)&xh,     g_xh);
    cudaGetSymbolAddress((void**)&xl,     g_xl);
    cudaGetSymbolAddress((void**)&wqh,    g_wqh);  cudaGetSymbolAddress((void**)&wql, g_wql);
    cudaGetSymbolAddress((void**)&wkh,    g_wkh);  cudaGetSymbolAddress((void**)&wkl, g_wkl);
    cudaGetSymbolAddress((void**)&wvh,    g_wvh);  cudaGetSymbolAddress((void**)&wvl, g_wvl);
    cudaGetSymbolAddress((void**)&woh,    g_woh);  cudaGetSymbolAddress((void**)&wol, g_wol);
    cudaGetSymbolAddress((void**)&pkth,   g_pkth); cudaGetSymbolAddress((void**)&pktl, g_pktl);
    cudaGetSymbolAddress((void**)&pvth,   g_pvth); cudaGetSymbolAddress((void**)&pvtl, g_pvtl);
    cudaGetSymbolAddress((void**)&xkth,   g_xkth); cudaGetSymbolAddress((void**)&xktl, g_xktl);
    cudaGetSymbolAddress((void**)&xvth,   g_xvth); cudaGetSymbolAddress((void**)&xvtl, g_xvtl);
    cudaGetSymbolAddress((void**)&keys2,  g_keys2);
    cudaGetSymbolAddress((void**)&vals2,  g_vals2);
    cudaGetSymbolAddress((void**)&keys_t, g_keys_t);
    cudaGetSymbolAddress((void**)&vals,   g_vals);
    cudaGetSymbolAddress((void**)&ctxh,   g_ctxh);
    cudaGetSymbolAddress((void**)&ctxl,   g_ctxl);

    cudaFuncSetAttribute(gemm_hsplit<false,0>, cudaFuncAttributeMaxDynamicSharedMemorySize, GEMM_SMEM);
    cudaFuncSetAttribute(gemm_hsplit<false,1>, cudaFuncAttributeMaxDynamicSharedMemorySize, GEMM_SMEM);
    cudaFuncSetAttribute(gemm_hsplit<true,0>,  cudaFuncAttributeMaxDynamicSharedMemorySize, GEMM_SMEM);
    cudaFuncSetAttribute(attn_kernel, cudaFuncAttributeMaxDynamicSharedMemorySize, ATTN_SMEM);

    // ---- pre-split inputs ----
    convert_split<<<(BB*LL*DD/4 + 255)/256, 256>>>(x,  xh,  xl,  BB*LL*DD/4);
    convert_split<<<(DD*DD/4 + 255)/256, 256>>>(Wq, wqh, wql, DD*DD/4);
    convert_split<<<(DD*DD/4 + 255)/256, 256>>>(Wk, wkh, wkl, DD*DD/4);
    convert_split<<<(DD*DD/4 + 255)/256, 256>>>(Wv, wvh, wvl, DD*DD/4);
    convert_split<<<(DD*DD/4 + 255)/256, 256>>>(Wo, woh, wol, DD*DD/4);
    transpose_split<<<dim3(KK/32, LL/32, 2), dim3(32, 8)>>>(
        proj_k, proj_v, pkth, pktl, pvth, pvtl);

    // q = x @ Wq^T -> f32 [8192,1024]
    gemm_hsplit<false,0><<<dim3(DD/128, MROWS/128, 1), 256, GEMM_SMEM>>>(
        xh, xl, 0, DD, wqh, wql, 0, DD, q, nullptr, 0, 0, DD, nullptr, DD, 1);

    // xkt[b] = Wk x_b^T -> half-split [B,D,L]
    gemm_hsplit<false,1><<<dim3(LL/128, DD/128, BB), 256, GEMM_SMEM>>>(
        wkh, wkl, 0, DD, xh, xl, (long)LL*DD, DD,
        xkth, xktl, (long)DD*LL, 0, LL, nullptr, DD, 1);

    // xvt[b]
    gemm_hsplit<false,1><<<dim3(LL/128, DD/128, BB), 256, GEMM_SMEM>>>(
        wvh, wvl, 0, DD, xh, xl, (long)LL*DD, DD,
        xvth, xvtl, (long)DD*LL, 0, LL, nullptr, DD, 1);

    // keys partials: [s][b][D,K] = xkt[b][:, s*1024:] @ pkt[:, s*1024:]^T
    gemm_hsplit<false,0><<<dim3(KK/128, DD/128, BB*2), 256, GEMM_SMEM>>>(
        xkth, xktl, (long)DD*LL, LL, pkth, pktl, 0, LL,
        keys2, nullptr, (long)DD*KK, (long)BB*DD*KK, KK, nullptr, LL/2, 2);

    // vals partials: [s][b][K,D]
    gemm_hsplit<false,0><<<dim3(DD/128, KK/128, BB*2), 256, GEMM_SMEM>>>(
        pvth, pvtl, 0, LL, xvth, xvtl, (long)DD*LL, LL,
        vals2, nullptr, (long)KK*DD, (long)BB*KK*DD, DD, nullptr, LL/2, 2);

    // reduce split-K partials
    add2<<<(BB*DD*KK/4 + 255)/256, 256>>>(keys2, keys2 + (size_t)BB*DD*KK, keys_t, BB*DD*KK/4);
    add2<<<(BB*KK*DD/4 + 255)/256, 256>>>(vals2, vals2 + (size_t)BB*KK*DD, vals,  BB*KK*DD/4);

    // attention core (emits ctx hi/lo)
    attn_kernel<<<dim3(LL/64, HH, BB), 256, ATTN_SMEM>>>();

    // out = ctx @ Wo^T + bo
    gemm_hsplit<true,0><<<dim3(DD/128, MROWS/128, 1), 256, GEMM_SMEM>>>(
        ctxh, ctxl, 0, DD, woh, wol, 0, DD, out, nullptr, 0, 0, DD, bo, DD, 1);
}